// round 2
// baseline (speedup 1.0000x reference)
#include <cuda_runtime.h>
#include <math.h>

#define BATCH  2
#define CDIM   256
#define NHEADS 4
#define HDIM   64
#define NTOK   4096
#define BHDIM  (BATCH * NHEADS)

// ---- scratch (static device globals: no runtime allocation) ----
__device__ float g_Q[BHDIM * NTOK * HDIM];   // [b,h,n,d]  8 MB
__device__ float g_K[BHDIM * NTOK * HDIM];   // 8 MB
__device__ float g_V[BHDIM * NTOK * HDIM];   // 8 MB
__device__ float g_O[BATCH * NTOK * CDIM];   // [b,n,c] c = h*64+d, 8 MB

// ============================================================================
// Kernel 1: QKV projection.  out[b,h,n,d] = sum_c x[b,c,n] * w[h*64+d, c] + bias
// grid (N/64, 12, B): blockIdx.y: which/4 selects q/k/v, y%4 selects co tile.
// ============================================================================
__global__ void __launch_bounds__(256) qkv_proj_kernel(
    const float* __restrict__ x,
    const float* __restrict__ wq, const float* __restrict__ bq,
    const float* __restrict__ wk, const float* __restrict__ bk,
    const float* __restrict__ wv, const float* __restrict__ bv)
{
    const int n0    = blockIdx.x * 64;
    const int which = blockIdx.y >> 2;
    const int co0   = (blockIdx.y & 3) * 64;
    const int b     = blockIdx.z;

    const float* w; const float* bias; float* out;
    if (which == 0)      { w = wq; bias = bq; out = g_Q; }
    else if (which == 1) { w = wk; bias = bk; out = g_K; }
    else                 { w = wv; bias = bv; out = g_V; }

    __shared__ float Xs[64][64];   // [c][n]
    __shared__ float Ws[64][65];   // [co][c], padded

    const int tid = threadIdx.x;
    const int tx = tid & 15, ty = tid >> 4;
    const int lr = tid >> 4;
    const int lc = (tid & 15) * 4;

    float acc[4][4] = {};

    for (int c0 = 0; c0 < CDIM; c0 += 64) {
        #pragma unroll
        for (int rr = 0; rr < 4; rr++) {
            int c = lr + rr * 16;
            float4 v = *(const float4*)&x[(size_t)(b * CDIM + c0 + c) * NTOK + n0 + lc];
            *(float4*)&Xs[c][lc] = v;
        }
        #pragma unroll
        for (int rr = 0; rr < 4; rr++) {
            int co = lr + rr * 16;
            float4 v = *(const float4*)&w[(size_t)(co0 + co) * CDIM + c0 + lc];
            Ws[co][lc + 0] = v.x; Ws[co][lc + 1] = v.y;
            Ws[co][lc + 2] = v.z; Ws[co][lc + 3] = v.w;
        }
        __syncthreads();

        #pragma unroll 16
        for (int c = 0; c < 64; c++) {
            float4 av = *(const float4*)&Xs[c][ty * 4];
            float a[4] = {av.x, av.y, av.z, av.w};         // n
            float bb[4];
            #pragma unroll
            for (int j = 0; j < 4; j++) bb[j] = Ws[tx * 4 + j][c];  // co
            #pragma unroll
            for (int i = 0; i < 4; i++)
                #pragma unroll
                for (int j = 0; j < 4; j++)
                    acc[i][j] += a[i] * bb[j];
        }
        __syncthreads();
    }

    const int h = co0 >> 6;   // co tile == one head (HD==64)
    #pragma unroll
    for (int i = 0; i < 4; i++) {
        int n = n0 + ty * 4 + i;
        float4 v;
        v.x = acc[i][0] + bias[co0 + tx * 4 + 0];
        v.y = acc[i][1] + bias[co0 + tx * 4 + 1];
        v.z = acc[i][2] + bias[co0 + tx * 4 + 2];
        v.w = acc[i][3] + bias[co0 + tx * 4 + 3];
        *(float4*)&out[((size_t)(b * NHEADS + h) * NTOK + n) * HDIM + tx * 4] = v;
    }
}

// ============================================================================
// Kernel 2: masked flash attention (fp32, online softmax).
// grid (N/64, B*NH), block 256. Block tile: 64 q x 64 k, thread tile 4x4.
// Mask is int32 (harness serializes numpy bool as int32).
// ============================================================================
__global__ void __launch_bounds__(256) attn_kernel(const int* __restrict__ mask)
{
    const int q0 = blockIdx.x * 64;
    const int bh = blockIdx.y;
    const int b  = bh >> 2;
    const int h  = bh & 3;

    const float* __restrict__ Qg = g_Q + (size_t)bh * NTOK * HDIM;
    const float* __restrict__ Kg = g_K + (size_t)bh * NTOK * HDIM;
    const float* __restrict__ Vg = g_V + (size_t)bh * NTOK * HDIM;

    __shared__ float Qs[64 * 64];
    __shared__ float KVs[64 * 64];
    __shared__ float Ps[64 * 64];

    const int tid = threadIdx.x;
    const int tx = tid & 15, ty = tid >> 4;

    // ---- load Q tile, transposed to [d][q], 16B-chunk XOR swizzle ----
    {
        const int d  = tid & 63;
        const int cb = tid >> 6;            // 0..3
        #pragma unroll
        for (int it = 0; it < 4; it++) {
            int ch = cb + it * 4;           // q-chunk 0..15
            float4 v;
            v.x = Qg[(size_t)(q0 + ch * 4 + 0) * HDIM + d];
            v.y = Qg[(size_t)(q0 + ch * 4 + 1) * HDIM + d];
            v.z = Qg[(size_t)(q0 + ch * 4 + 2) * HDIM + d];
            v.w = Qg[(size_t)(q0 + ch * 4 + 3) * HDIM + d];
            *(float4*)&Qs[d * 64 + 4 * (ch ^ (d & 15))] = v;
        }
    }

    float m_i[4], l_i[4], o[4][4];
    #pragma unroll
    for (int i = 0; i < 4; i++) {
        m_i[i] = -INFINITY; l_i[i] = 0.0f;
        #pragma unroll
        for (int j = 0; j < 4; j++) o[i][j] = 0.0f;
    }

    const float scale = 0.125f;             // HD^-0.5
    const size_t mbase = (size_t)b * NTOK * NTOK;

    for (int kt = 0; kt < NTOK / 64; kt++) {
        const int k0 = kt * 64;

        __syncthreads();                    // prior GEMM2 / Q-load done
        // ---- load K tile into KVs as [d][k], swizzled ----
        {
            const int d  = tid & 63;
            const int cb = tid >> 6;
            #pragma unroll
            for (int it = 0; it < 4; it++) {
                int ch = cb + it * 4;
                float4 v;
                v.x = Kg[(size_t)(k0 + ch * 4 + 0) * HDIM + d];
                v.y = Kg[(size_t)(k0 + ch * 4 + 1) * HDIM + d];
                v.z = Kg[(size_t)(k0 + ch * 4 + 2) * HDIM + d];
                v.w = Kg[(size_t)(k0 + ch * 4 + 3) * HDIM + d];
                *(float4*)&KVs[d * 64 + 4 * (ch ^ (d & 15))] = v;
            }
        }
        __syncthreads();

        // ---- S = Q K^T : outer product over d ----
        float s[4][4] = {};
        #pragma unroll 8
        for (int d = 0; d < 64; d++) {
            float4 av = *(const float4*)&Qs[d * 64 + 4 * (ty ^ (d & 15))];
            float4 bv = *(const float4*)&KVs[d * 64 + 4 * (tx ^ (d & 15))];
            float a[4] = {av.x, av.y, av.z, av.w};
            float bb[4] = {bv.x, bv.y, bv.z, bv.w};
            #pragma unroll
            for (int i = 0; i < 4; i++)
                #pragma unroll
                for (int j = 0; j < 4; j++)
                    s[i][j] += a[i] * bb[j];
        }

        // ---- mask + scale + online softmax (rows reduce over 16 lanes) ----
        #pragma unroll
        for (int i = 0; i < 4; i++) {
            const int4 mv = *(const int4*)(mask + mbase
                               + (size_t)(q0 + ty * 4 + i) * NTOK + k0 + tx * 4);
            s[i][0] = mv.x ? s[i][0] * scale : -INFINITY;
            s[i][1] = mv.y ? s[i][1] * scale : -INFINITY;
            s[i][2] = mv.z ? s[i][2] * scale : -INFINITY;
            s[i][3] = mv.w ? s[i][3] * scale : -INFINITY;

            float tm = fmaxf(fmaxf(s[i][0], s[i][1]), fmaxf(s[i][2], s[i][3]));
            #pragma unroll
            for (int off = 1; off < 16; off <<= 1)
                tm = fmaxf(tm, __shfl_xor_sync(0xffffffffu, tm, off));

            float mn = fmaxf(m_i[i], tm);
            float alpha = (mn == -INFINITY) ? 1.0f : __expf(m_i[i] - mn);

            float rs = 0.0f;
            #pragma unroll
            for (int j = 0; j < 4; j++) {
                float p = (s[i][j] == -INFINITY) ? 0.0f : __expf(s[i][j] - mn);
                s[i][j] = p;
                rs += p;
            }
            #pragma unroll
            for (int off = 1; off < 16; off <<= 1)
                rs += __shfl_xor_sync(0xffffffffu, rs, off);

            l_i[i] = l_i[i] * alpha + rs;
            m_i[i] = mn;
            #pragma unroll
            for (int j = 0; j < 4; j++) o[i][j] *= alpha;
        }

        __syncthreads();                    // S-phase reads of KVs done
        // ---- store P^T [k][q] swizzled; load V into KVs as [k][d] ----
        #pragma unroll
        for (int j = 0; j < 4; j++) {
            int k = tx * 4 + j;
            float4 pv;
            pv.x = s[0][j]; pv.y = s[1][j]; pv.z = s[2][j]; pv.w = s[3][j];
            *(float4*)&Ps[k * 64 + 4 * (ty ^ (k & 15))] = pv;
        }
        {
            const int lr2 = tid >> 4;
            const int lc2 = (tid & 15) * 4;
            #pragma unroll
            for (int rr = 0; rr < 4; rr++) {
                int k = lr2 + rr * 16;
                *(float4*)&KVs[k * 64 + lc2] =
                    *(const float4*)&Vg[(size_t)(k0 + k) * HDIM + lc2];
            }
        }
        __syncthreads();

        // ---- O += P V : outer product over k ----
        #pragma unroll 8
        for (int k = 0; k < 64; k++) {
            float4 av = *(const float4*)&Ps[k * 64 + 4 * (ty ^ (k & 15))];
            float4 bv = *(const float4*)&KVs[k * 64 + tx * 4];
            float a[4] = {av.x, av.y, av.z, av.w};
            float bb[4] = {bv.x, bv.y, bv.z, bv.w};
            #pragma unroll
            for (int i = 0; i < 4; i++)
                #pragma unroll
                for (int j = 0; j < 4; j++)
                    o[i][j] += a[i] * bb[j];
        }
    }

    // ---- epilogue: normalize and store [b][n][c], c = h*64 + d ----
    #pragma unroll
    for (int i = 0; i < 4; i++) {
        float inv = 1.0f / l_i[i];
        float4 v;
        v.x = o[i][0] * inv; v.y = o[i][1] * inv;
        v.z = o[i][2] * inv; v.w = o[i][3] * inv;
        *(float4*)&g_O[((size_t)(b * NTOK + q0 + ty * 4 + i)) * CDIM + h * 64 + tx * 4] = v;
    }
}

// ============================================================================
// Kernel 3: output projection.  y[b,co,n] = sum_c O[b,n,c]*wo[co,c] + bo[co]
// grid (N/64, C/64, B), block 256.
// ============================================================================
__global__ void __launch_bounds__(256) out_proj_kernel(
    const float* __restrict__ wo, const float* __restrict__ bo,
    float* __restrict__ y)
{
    const int n0  = blockIdx.x * 64;
    const int co0 = blockIdx.y * 64;
    const int b   = blockIdx.z;

    __shared__ float Os[64][65];    // [c][n]
    __shared__ float Wos[64][65];   // [co][c]

    const int tid = threadIdx.x;
    const int tx = tid & 15, ty = tid >> 4;
    const int lr = tid >> 4;
    const int lc = (tid & 15) * 4;

    float acc[4][4] = {};

    for (int c0 = 0; c0 < CDIM; c0 += 64) {
        #pragma unroll
        for (int rr = 0; rr < 4; rr++) {
            int n = lr + rr * 16;
            float4 v = *(const float4*)&g_O[((size_t)(b * NTOK + n0 + n)) * CDIM + c0 + lc];
            Os[lc + 0][n] = v.x; Os[lc + 1][n] = v.y;
            Os[lc + 2][n] = v.z; Os[lc + 3][n] = v.w;
        }
        #pragma unroll
        for (int rr = 0; rr < 4; rr++) {
            int co = lr + rr * 16;
            float4 v = *(const float4*)&wo[(size_t)(co0 + co) * CDIM + c0 + lc];
            Wos[co][lc + 0] = v.x; Wos[co][lc + 1] = v.y;
            Wos[co][lc + 2] = v.z; Wos[co][lc + 3] = v.w;
        }
        __syncthreads();

        #pragma unroll 16
        for (int c = 0; c < 64; c++) {
            float a[4], bb[4];
            #pragma unroll
            for (int i = 0; i < 4; i++) a[i] = Wos[ty * 4 + i][c];   // co
            #pragma unroll
            for (int j = 0; j < 4; j++) bb[j] = Os[c][tx * 4 + j];   // n
            #pragma unroll
            for (int i = 0; i < 4; i++)
                #pragma unroll
                for (int j = 0; j < 4; j++)
                    acc[i][j] += a[i] * bb[j];
        }
        __syncthreads();
    }

    #pragma unroll
    for (int i = 0; i < 4; i++) {
        int co = co0 + ty * 4 + i;
        float bbias = bo[co];
        float4 v;
        v.x = acc[i][0] + bbias; v.y = acc[i][1] + bbias;
        v.z = acc[i][2] + bbias; v.w = acc[i][3] + bbias;
        *(float4*)&y[((size_t)(b * CDIM + co)) * NTOK + n0 + tx * 4] = v;
    }
}

// ============================================================================
// Launch
// ============================================================================
extern "C" void kernel_launch(void* const* d_in, const int* in_sizes, int n_in,
                              void* d_out, int out_size)
{
    const float* x    = (const float*)d_in[0];
    const int*   mask = (const int*)d_in[1];   // numpy bool serialized as int32
    const float* wq   = (const float*)d_in[2];
    const float* bq   = (const float*)d_in[3];
    const float* wk   = (const float*)d_in[4];
    const float* bk   = (const float*)d_in[5];
    const float* wv   = (const float*)d_in[6];
    const float* bv   = (const float*)d_in[7];
    const float* wo   = (const float*)d_in[8];
    const float* bo   = (const float*)d_in[9];
    float* y = (float*)d_out;

    qkv_proj_kernel<<<dim3(NTOK / 64, 12, BATCH), 256>>>(x, wq, bq, wk, bk, wv, bv);
    attn_kernel<<<dim3(NTOK / 64, BHDIM), 256>>>(mask);
    out_proj_kernel<<<dim3(NTOK / 64, CDIM / 64, BATCH), 256>>>(wo, bo, y);
}

// round 3
// speedup vs baseline: 1.0538x; 1.0538x over previous
#include <cuda_runtime.h>
#include <math.h>

#define BATCH  2
#define CDIM   256
#define NHEADS 4
#define HDIM   64
#define NTOK   4096
#define BHDIM  (BATCH * NHEADS)

// ---- scratch (static device globals: no runtime allocation) ----
__device__ float g_Q[BHDIM * NTOK * HDIM];   // [b,h,n,d]  8 MB
__device__ float g_K[BHDIM * NTOK * HDIM];   // 8 MB
__device__ float g_V[BHDIM * NTOK * HDIM];   // 8 MB
__device__ float g_O[BATCH * NTOK * CDIM];   // [b,n,c] c = h*64+d, 8 MB

// ============================================================================
// Kernel 1: QKV projection.  out[b,h,n,d] = sum_c x[b,c,n] * w[h*64+d, c] + bias
// grid (N/64, 12, B): blockIdx.y: which/4 selects q/k/v, y%4 selects co tile.
// ============================================================================
__global__ void __launch_bounds__(256) qkv_proj_kernel(
    const float* __restrict__ x,
    const float* __restrict__ wq, const float* __restrict__ bq,
    const float* __restrict__ wk, const float* __restrict__ bk,
    const float* __restrict__ wv, const float* __restrict__ bv)
{
    const int n0    = blockIdx.x * 64;
    const int which = blockIdx.y >> 2;
    const int co0   = (blockIdx.y & 3) * 64;
    const int b     = blockIdx.z;

    const float* w; const float* bias; float* out;
    if (which == 0)      { w = wq; bias = bq; out = g_Q; }
    else if (which == 1) { w = wk; bias = bk; out = g_K; }
    else                 { w = wv; bias = bv; out = g_V; }

    __shared__ float Xs[64][64];   // [c][n]
    __shared__ float Ws[64][65];   // [co][c], padded

    const int tid = threadIdx.x;
    const int tx = tid & 15, ty = tid >> 4;
    const int lr = tid >> 4;
    const int lc = (tid & 15) * 4;

    float acc[4][4] = {};

    for (int c0 = 0; c0 < CDIM; c0 += 64) {
        #pragma unroll
        for (int rr = 0; rr < 4; rr++) {
            int c = lr + rr * 16;
            float4 v = *(const float4*)&x[(size_t)(b * CDIM + c0 + c) * NTOK + n0 + lc];
            *(float4*)&Xs[c][lc] = v;
        }
        #pragma unroll
        for (int rr = 0; rr < 4; rr++) {
            int co = lr + rr * 16;
            float4 v = *(const float4*)&w[(size_t)(co0 + co) * CDIM + c0 + lc];
            Ws[co][lc + 0] = v.x; Ws[co][lc + 1] = v.y;
            Ws[co][lc + 2] = v.z; Ws[co][lc + 3] = v.w;
        }
        __syncthreads();

        #pragma unroll 16
        for (int c = 0; c < 64; c++) {
            float4 av = *(const float4*)&Xs[c][ty * 4];
            float a[4] = {av.x, av.y, av.z, av.w};         // n
            float bb[4];
            #pragma unroll
            for (int j = 0; j < 4; j++) bb[j] = Ws[tx * 4 + j][c];  // co
            #pragma unroll
            for (int i = 0; i < 4; i++)
                #pragma unroll
                for (int j = 0; j < 4; j++)
                    acc[i][j] += a[i] * bb[j];
        }
        __syncthreads();
    }

    const int h = co0 >> 6;   // co tile == one head (HD==64)
    #pragma unroll
    for (int i = 0; i < 4; i++) {
        int n = n0 + ty * 4 + i;
        float4 v;
        v.x = acc[i][0] + bias[co0 + tx * 4 + 0];
        v.y = acc[i][1] + bias[co0 + tx * 4 + 1];
        v.z = acc[i][2] + bias[co0 + tx * 4 + 2];
        v.w = acc[i][3] + bias[co0 + tx * 4 + 3];
        *(float4*)&out[((size_t)(b * NHEADS + h) * NTOK + n) * HDIM + tx * 4] = v;
    }
}

// ============================================================================
// Kernel 2: masked flash attention (fp32, online softmax).
// grid (N/64, B*NH), block 256. Block tile: 64 q x 64 k, thread tile 4x4.
// Mask is int32 (harness serializes numpy bool as int32).
// ============================================================================
__global__ void __launch_bounds__(256) attn_kernel(const int* __restrict__ mask)
{
    const int q0 = blockIdx.x * 64;
    const int bh = blockIdx.y;
    const int b  = bh >> 2;
    const int h  = bh & 3;

    const float* __restrict__ Qg = g_Q + (size_t)bh * NTOK * HDIM;
    const float* __restrict__ Kg = g_K + (size_t)bh * NTOK * HDIM;
    const float* __restrict__ Vg = g_V + (size_t)bh * NTOK * HDIM;

    __shared__ float Qs[64 * 64];
    __shared__ float KVs[64 * 64];
    __shared__ float Ps[64 * 64];

    const int tid = threadIdx.x;
    const int tx = tid & 15, ty = tid >> 4;

    // ---- load Q tile, transposed to [d][q], 16B-chunk XOR swizzle ----
    {
        const int d  = tid & 63;
        const int cb = tid >> 6;            // 0..3
        #pragma unroll
        for (int it = 0; it < 4; it++) {
            int ch = cb + it * 4;           // q-chunk 0..15
            float4 v;
            v.x = Qg[(size_t)(q0 + ch * 4 + 0) * HDIM + d];
            v.y = Qg[(size_t)(q0 + ch * 4 + 1) * HDIM + d];
            v.z = Qg[(size_t)(q0 + ch * 4 + 2) * HDIM + d];
            v.w = Qg[(size_t)(q0 + ch * 4 + 3) * HDIM + d];
            *(float4*)&Qs[d * 64 + 4 * (ch ^ (d & 15))] = v;
        }
    }

    float m_i[4], l_i[4], o[4][4];
    #pragma unroll
    for (int i = 0; i < 4; i++) {
        m_i[i] = -INFINITY; l_i[i] = 0.0f;
        #pragma unroll
        for (int j = 0; j < 4; j++) o[i][j] = 0.0f;
    }

    const float scale = 0.125f;             // HD^-0.5
    const size_t mbase = (size_t)b * NTOK * NTOK;

    for (int kt = 0; kt < NTOK / 64; kt++) {
        const int k0 = kt * 64;

        __syncthreads();                    // prior GEMM2 / Q-load done
        // ---- load K tile into KVs as [d][k], swizzled ----
        {
            const int d  = tid & 63;
            const int cb = tid >> 6;
            #pragma unroll
            for (int it = 0; it < 4; it++) {
                int ch = cb + it * 4;
                float4 v;
                v.x = Kg[(size_t)(k0 + ch * 4 + 0) * HDIM + d];
                v.y = Kg[(size_t)(k0 + ch * 4 + 1) * HDIM + d];
                v.z = Kg[(size_t)(k0 + ch * 4 + 2) * HDIM + d];
                v.w = Kg[(size_t)(k0 + ch * 4 + 3) * HDIM + d];
                *(float4*)&KVs[d * 64 + 4 * (ch ^ (d & 15))] = v;
            }
        }
        __syncthreads();

        // ---- S = Q K^T : outer product over d ----
        float s[4][4] = {};
        #pragma unroll 8
        for (int d = 0; d < 64; d++) {
            float4 av = *(const float4*)&Qs[d * 64 + 4 * (ty ^ (d & 15))];
            float4 bv = *(const float4*)&KVs[d * 64 + 4 * (tx ^ (d & 15))];
            float a[4] = {av.x, av.y, av.z, av.w};
            float bb[4] = {bv.x, bv.y, bv.z, bv.w};
            #pragma unroll
            for (int i = 0; i < 4; i++)
                #pragma unroll
                for (int j = 0; j < 4; j++)
                    s[i][j] += a[i] * bb[j];
        }

        // ---- mask + scale + online softmax (rows reduce over 16 lanes) ----
        #pragma unroll
        for (int i = 0; i < 4; i++) {
            const int4 mv = *(const int4*)(mask + mbase
                               + (size_t)(q0 + ty * 4 + i) * NTOK + k0 + tx * 4);
            s[i][0] = mv.x ? s[i][0] * scale : -INFINITY;
            s[i][1] = mv.y ? s[i][1] * scale : -INFINITY;
            s[i][2] = mv.z ? s[i][2] * scale : -INFINITY;
            s[i][3] = mv.w ? s[i][3] * scale : -INFINITY;

            float tm = fmaxf(fmaxf(s[i][0], s[i][1]), fmaxf(s[i][2], s[i][3]));
            #pragma unroll
            for (int off = 1; off < 16; off <<= 1)
                tm = fmaxf(tm, __shfl_xor_sync(0xffffffffu, tm, off));

            float mn = fmaxf(m_i[i], tm);
            float alpha = (mn == -INFINITY) ? 1.0f : __expf(m_i[i] - mn);

            float rs = 0.0f;
            #pragma unroll
            for (int j = 0; j < 4; j++) {
                float p = (s[i][j] == -INFINITY) ? 0.0f : __expf(s[i][j] - mn);
                s[i][j] = p;
                rs += p;
            }
            #pragma unroll
            for (int off = 1; off < 16; off <<= 1)
                rs += __shfl_xor_sync(0xffffffffu, rs, off);

            l_i[i] = l_i[i] * alpha + rs;
            m_i[i] = mn;
            #pragma unroll
            for (int j = 0; j < 4; j++) o[i][j] *= alpha;
        }

        __syncthreads();                    // S-phase reads of KVs done
        // ---- store P^T [k][q] swizzled; load V into KVs as [k][d] ----
        #pragma unroll
        for (int j = 0; j < 4; j++) {
            int k = tx * 4 + j;
            float4 pv;
            pv.x = s[0][j]; pv.y = s[1][j]; pv.z = s[2][j]; pv.w = s[3][j];
            *(float4*)&Ps[k * 64 + 4 * (ty ^ (k & 15))] = pv;
        }
        {
            const int lr2 = tid >> 4;
            const int lc2 = (tid & 15) * 4;
            #pragma unroll
            for (int rr = 0; rr < 4; rr++) {
                int k = lr2 + rr * 16;
                *(float4*)&KVs[k * 64 + lc2] =
                    *(const float4*)&Vg[(size_t)(k0 + k) * HDIM + lc2];
            }
        }
        __syncthreads();

        // ---- O += P V : outer product over k ----
        #pragma unroll 8
        for (int k = 0; k < 64; k++) {
            float4 av = *(const float4*)&Ps[k * 64 + 4 * (ty ^ (k & 15))];
            float4 bv = *(const float4*)&KVs[k * 64 + tx * 4];
            float a[4] = {av.x, av.y, av.z, av.w};
            float bb[4] = {bv.x, bv.y, bv.z, bv.w};
            #pragma unroll
            for (int i = 0; i < 4; i++)
                #pragma unroll
                for (int j = 0; j < 4; j++)
                    o[i][j] += a[i] * bb[j];
        }
    }

    // ---- epilogue: normalize and store [b][n][c], c = h*64 + d ----
    #pragma unroll
    for (int i = 0; i < 4; i++) {
        float inv = 1.0f / l_i[i];
        float4 v;
        v.x = o[i][0] * inv; v.y = o[i][1] * inv;
        v.z = o[i][2] * inv; v.w = o[i][3] * inv;
        *(float4*)&g_O[((size_t)(b * NTOK + q0 + ty * 4 + i)) * CDIM + h * 64 + tx * 4] = v;
    }
}

// ============================================================================
// Kernel 3: output projection.  y[b,co,n] = sum_c O[b,n,c]*wo[co,c] + bo[co]
// grid (N/64, C/64, B), block 256.
// ============================================================================
__global__ void __launch_bounds__(256) out_proj_kernel(
    const float* __restrict__ wo, const float* __restrict__ bo,
    float* __restrict__ y)
{
    const int n0  = blockIdx.x * 64;
    const int co0 = blockIdx.y * 64;
    const int b   = blockIdx.z;

    __shared__ float Os[64][65];    // [c][n]
    __shared__ float Wos[64][65];   // [co][c]

    const int tid = threadIdx.x;
    const int tx = tid & 15, ty = tid >> 4;
    const int lr = tid >> 4;
    const int lc = (tid & 15) * 4;

    float acc[4][4] = {};

    for (int c0 = 0; c0 < CDIM; c0 += 64) {
        #pragma unroll
        for (int rr = 0; rr < 4; rr++) {
            int n = lr + rr * 16;
            float4 v = *(const float4*)&g_O[((size_t)(b * NTOK + n0 + n)) * CDIM + c0 + lc];
            Os[lc + 0][n] = v.x; Os[lc + 1][n] = v.y;
            Os[lc + 2][n] = v.z; Os[lc + 3][n] = v.w;
        }
        #pragma unroll
        for (int rr = 0; rr < 4; rr++) {
            int co = lr + rr * 16;
            float4 v = *(const float4*)&wo[(size_t)(co0 + co) * CDIM + c0 + lc];
            Wos[co][lc + 0] = v.x; Wos[co][lc + 1] = v.y;
            Wos[co][lc + 2] = v.z; Wos[co][lc + 3] = v.w;
        }
        __syncthreads();

        #pragma unroll 16
        for (int c = 0; c < 64; c++) {
            float a[4], bb[4];
            #pragma unroll
            for (int i = 0; i < 4; i++) a[i] = Wos[ty * 4 + i][c];   // co
            #pragma unroll
            for (int j = 0; j < 4; j++) bb[j] = Os[c][tx * 4 + j];   // n
            #pragma unroll
            for (int i = 0; i < 4; i++)
                #pragma unroll
                for (int j = 0; j < 4; j++)
                    acc[i][j] += a[i] * bb[j];
        }
        __syncthreads();
    }

    #pragma unroll
    for (int i = 0; i < 4; i++) {
        int co = co0 + ty * 4 + i;
        float bbias = bo[co];
        float4 v;
        v.x = acc[i][0] + bbias; v.y = acc[i][1] + bbias;
        v.z = acc[i][2] + bbias; v.w = acc[i][3] + bbias;
        *(float4*)&y[((size_t)(b * CDIM + co)) * NTOK + n0 + tx * 4] = v;
    }
}

// ============================================================================
// Launch
// ============================================================================
extern "C" void kernel_launch(void* const* d_in, const int* in_sizes, int n_in,
                              void* d_out, int out_size)
{
    const float* x    = (const float*)d_in[0];
    const int*   mask = (const int*)d_in[1];   // numpy bool serialized as int32
    const float* wq   = (const float*)d_in[2];
    const float* bq   = (const float*)d_in[3];
    const float* wk   = (const float*)d_in[4];
    const float* bk   = (const float*)d_in[5];
    const float* wv   = (const float*)d_in[6];
    const float* bv   = (const float*)d_in[7];
    const float* wo   = (const float*)d_in[8];
    const float* bo   = (const float*)d_in[9];
    float* y = (float*)d_out;

    qkv_proj_kernel<<<dim3(NTOK / 64, 12, BATCH), 256>>>(x, wq, bq, wk, bk, wv, bv);
    attn_kernel<<<dim3(NTOK / 64, BHDIM), 256>>>(mask);
    out_proj_kernel<<<dim3(NTOK / 64, CDIM / 64, BATCH), 256>>>(wo, bo, y);
}

// round 4
// speedup vs baseline: 1.1524x; 1.0935x over previous
#include <cuda_runtime.h>
#include <math.h>

#define BATCH  2
#define CDIM   256
#define NHEADS 4
#define HDIM   64
#define NTOK   4096
#define BHDIM  (BATCH * NHEADS)

// ---- scratch (static device globals: no runtime allocation) ----
__device__ float g_Q[BHDIM * NTOK * HDIM];   // [b,h,n,d]  8 MB
__device__ float g_K[BHDIM * NTOK * HDIM];   // 8 MB
__device__ float g_V[BHDIM * NTOK * HDIM];   // 8 MB
__device__ float g_O[BATCH * NTOK * CDIM];   // [b,n,c] c = h*64+d, 8 MB

// ---- packed fp32x2 helpers (sm_100+: fma.rn.f32x2 on 64-bit register pairs) --
__device__ __forceinline__ unsigned long long pack2(float lo, float hi) {
    unsigned long long r;
    asm("mov.b64 %0, {%1, %2};" : "=l"(r) : "f"(lo), "f"(hi));
    return r;
}
__device__ __forceinline__ void unpack2(unsigned long long v, float& lo, float& hi) {
    asm("mov.b64 {%0, %1}, %2;" : "=f"(lo), "=f"(hi) : "l"(v));
}
__device__ __forceinline__ void ffma2(unsigned long long& d,
                                      unsigned long long a, unsigned long long b) {
    asm("fma.rn.f32x2 %0, %1, %2, %0;" : "+l"(d) : "l"(a), "l"(b));
}
__device__ __forceinline__ void fmul2(unsigned long long& d, unsigned long long a) {
    asm("mul.rn.f32x2 %0, %0, %1;" : "+l"(d) : "l"(a));
}

// ============================================================================
// Kernel 1: QKV projection.  out[b,h,n,d] = sum_c x[b,c,n] * w[h*64+d, c] + bias
// acc packed along n (pairs), weight scalar duplicated.
// ============================================================================
__global__ void __launch_bounds__(256) qkv_proj_kernel(
    const float* __restrict__ x,
    const float* __restrict__ wq, const float* __restrict__ bq,
    const float* __restrict__ wk, const float* __restrict__ bk,
    const float* __restrict__ wv, const float* __restrict__ bv)
{
    const int n0    = blockIdx.x * 64;
    const int which = blockIdx.y >> 2;
    const int co0   = (blockIdx.y & 3) * 64;
    const int b     = blockIdx.z;

    const float* w; const float* bias; float* out;
    if (which == 0)      { w = wq; bias = bq; out = g_Q; }
    else if (which == 1) { w = wk; bias = bk; out = g_K; }
    else                 { w = wv; bias = bv; out = g_V; }

    __shared__ float Xs[64][64];   // [c][n]
    __shared__ float Ws[64][65];   // [co][c], padded

    const int tid = threadIdx.x;
    const int tx = tid & 15, ty = tid >> 4;
    const int lr = tid >> 4;
    const int lc = (tid & 15) * 4;

    // acc2[j][i2]: j = co (4), i2 = n-pair (2)
    unsigned long long acc2[4][2];
    #pragma unroll
    for (int j = 0; j < 4; j++) { acc2[j][0] = 0ull; acc2[j][1] = 0ull; }

    for (int c0 = 0; c0 < CDIM; c0 += 64) {
        #pragma unroll
        for (int rr = 0; rr < 4; rr++) {
            int c = lr + rr * 16;
            float4 v = *(const float4*)&x[(size_t)(b * CDIM + c0 + c) * NTOK + n0 + lc];
            *(float4*)&Xs[c][lc] = v;
        }
        #pragma unroll
        for (int rr = 0; rr < 4; rr++) {
            int co = lr + rr * 16;
            float4 v = *(const float4*)&w[(size_t)(co0 + co) * CDIM + c0 + lc];
            Ws[co][lc + 0] = v.x; Ws[co][lc + 1] = v.y;
            Ws[co][lc + 2] = v.z; Ws[co][lc + 3] = v.w;
        }
        __syncthreads();

        #pragma unroll 8
        for (int c = 0; c < 64; c++) {
            ulonglong2 au = *(const ulonglong2*)&Xs[c][ty * 4];   // n pairs
            #pragma unroll
            for (int j = 0; j < 4; j++) {
                float bb = Ws[tx * 4 + j][c];
                unsigned long long bd = pack2(bb, bb);
                ffma2(acc2[j][0], bd, au.x);
                ffma2(acc2[j][1], bd, au.y);
            }
        }
        __syncthreads();
    }

    // unpack: accf[i][j], i = n, j = co
    float accf[4][4];
    #pragma unroll
    for (int j = 0; j < 4; j++) {
        unpack2(acc2[j][0], accf[0][j], accf[1][j]);
        unpack2(acc2[j][1], accf[2][j], accf[3][j]);
    }

    const int h = co0 >> 6;   // co tile == one head (HD==64)
    #pragma unroll
    for (int i = 0; i < 4; i++) {
        int n = n0 + ty * 4 + i;
        float4 v;
        v.x = accf[i][0] + bias[co0 + tx * 4 + 0];
        v.y = accf[i][1] + bias[co0 + tx * 4 + 1];
        v.z = accf[i][2] + bias[co0 + tx * 4 + 2];
        v.w = accf[i][3] + bias[co0 + tx * 4 + 3];
        *(float4*)&out[((size_t)(b * NHEADS + h) * NTOK + n) * HDIM + tx * 4] = v;
    }
}

// ============================================================================
// Kernel 2: masked flash attention (fp32, online softmax, FFMA2 GEMMs).
// grid (N/64, B*NH), block 256. Block tile: 64 q x 64 k, thread tile 4x4.
// ============================================================================
__global__ void __launch_bounds__(256) attn_kernel(const int* __restrict__ mask)
{
    const int q0 = blockIdx.x * 64;
    const int bh = blockIdx.y;
    const int b  = bh >> 2;
    const int h  = bh & 3;

    const float* __restrict__ Qg = g_Q + (size_t)bh * NTOK * HDIM;
    const float* __restrict__ Kg = g_K + (size_t)bh * NTOK * HDIM;
    const float* __restrict__ Vg = g_V + (size_t)bh * NTOK * HDIM;

    __shared__ float Qs[64 * 64];
    __shared__ float KVs[64 * 64];
    __shared__ float Ps[64 * 64];

    const int tid = threadIdx.x;
    const int tx = tid & 15, ty = tid >> 4;

    // ---- load Q tile, transposed to [d][q], 16B-chunk XOR swizzle ----
    {
        const int d  = tid & 63;
        const int cb = tid >> 6;            // 0..3
        #pragma unroll
        for (int it = 0; it < 4; it++) {
            int ch = cb + it * 4;           // q-chunk 0..15
            float4 v;
            v.x = Qg[(size_t)(q0 + ch * 4 + 0) * HDIM + d];
            v.y = Qg[(size_t)(q0 + ch * 4 + 1) * HDIM + d];
            v.z = Qg[(size_t)(q0 + ch * 4 + 2) * HDIM + d];
            v.w = Qg[(size_t)(q0 + ch * 4 + 3) * HDIM + d];
            *(float4*)&Qs[d * 64 + 4 * (ch ^ (d & 15))] = v;
        }
    }

    float m_i[4], l_i[4];
    unsigned long long o2[4][2];            // [i_q][d-pair half] packed over d
    #pragma unroll
    for (int i = 0; i < 4; i++) {
        m_i[i] = -INFINITY; l_i[i] = 0.0f;
        o2[i][0] = 0ull; o2[i][1] = 0ull;
    }

    const float scale = 0.125f;             // HD^-0.5
    const size_t mbase = (size_t)b * NTOK * NTOK;

    for (int kt = 0; kt < NTOK / 64; kt++) {
        const int k0 = kt * 64;

        __syncthreads();                    // prior GEMM2 / Q-load done
        // ---- load K tile into KVs as [d][k], swizzled ----
        {
            const int d  = tid & 63;
            const int cb = tid >> 6;
            #pragma unroll
            for (int it = 0; it < 4; it++) {
                int ch = cb + it * 4;
                float4 v;
                v.x = Kg[(size_t)(k0 + ch * 4 + 0) * HDIM + d];
                v.y = Kg[(size_t)(k0 + ch * 4 + 1) * HDIM + d];
                v.z = Kg[(size_t)(k0 + ch * 4 + 2) * HDIM + d];
                v.w = Kg[(size_t)(k0 + ch * 4 + 3) * HDIM + d];
                *(float4*)&KVs[d * 64 + 4 * (ch ^ (d & 15))] = v;
            }
        }
        __syncthreads();

        // ---- S = Q K^T : outer product over d, acc packed over k-pairs ----
        unsigned long long s2[4][2];
        #pragma unroll
        for (int i = 0; i < 4; i++) { s2[i][0] = 0ull; s2[i][1] = 0ull; }

        #pragma unroll 8
        for (int d = 0; d < 64; d++) {
            float4 av = *(const float4*)&Qs[d * 64 + 4 * (ty ^ (d & 15))];
            ulonglong2 bu = *(const ulonglong2*)&KVs[d * 64 + 4 * (tx ^ (d & 15))];
            unsigned long long a0 = pack2(av.x, av.x);
            unsigned long long a1 = pack2(av.y, av.y);
            unsigned long long a2 = pack2(av.z, av.z);
            unsigned long long a3 = pack2(av.w, av.w);
            ffma2(s2[0][0], a0, bu.x); ffma2(s2[0][1], a0, bu.y);
            ffma2(s2[1][0], a1, bu.x); ffma2(s2[1][1], a1, bu.y);
            ffma2(s2[2][0], a2, bu.x); ffma2(s2[2][1], a2, bu.y);
            ffma2(s2[3][0], a3, bu.x); ffma2(s2[3][1], a3, bu.y);
        }

        float s[4][4];
        #pragma unroll
        for (int i = 0; i < 4; i++) {
            unpack2(s2[i][0], s[i][0], s[i][1]);
            unpack2(s2[i][1], s[i][2], s[i][3]);
        }

        // ---- mask + scale + online softmax (rows reduce over 16 lanes) ----
        #pragma unroll
        for (int i = 0; i < 4; i++) {
            const int4 mv = *(const int4*)(mask + mbase
                               + (size_t)(q0 + ty * 4 + i) * NTOK + k0 + tx * 4);
            s[i][0] = mv.x ? s[i][0] * scale : -INFINITY;
            s[i][1] = mv.y ? s[i][1] * scale : -INFINITY;
            s[i][2] = mv.z ? s[i][2] * scale : -INFINITY;
            s[i][3] = mv.w ? s[i][3] * scale : -INFINITY;

            float tm = fmaxf(fmaxf(s[i][0], s[i][1]), fmaxf(s[i][2], s[i][3]));
            #pragma unroll
            for (int off = 1; off < 16; off <<= 1)
                tm = fmaxf(tm, __shfl_xor_sync(0xffffffffu, tm, off));

            float mn = fmaxf(m_i[i], tm);
            float alpha = (mn == -INFINITY) ? 1.0f : __expf(m_i[i] - mn);

            float rs = 0.0f;
            #pragma unroll
            for (int j = 0; j < 4; j++) {
                float p = (s[i][j] == -INFINITY) ? 0.0f : __expf(s[i][j] - mn);
                s[i][j] = p;
                rs += p;
            }
            #pragma unroll
            for (int off = 1; off < 16; off <<= 1)
                rs += __shfl_xor_sync(0xffffffffu, rs, off);

            l_i[i] = l_i[i] * alpha + rs;
            m_i[i] = mn;
            unsigned long long ad = pack2(alpha, alpha);
            fmul2(o2[i][0], ad);
            fmul2(o2[i][1], ad);
        }

        __syncthreads();                    // S-phase reads of KVs done
        // ---- store P^T [k][q] swizzled; load V into KVs as [k][d] ----
        #pragma unroll
        for (int j = 0; j < 4; j++) {
            int k = tx * 4 + j;
            float4 pv;
            pv.x = s[0][j]; pv.y = s[1][j]; pv.z = s[2][j]; pv.w = s[3][j];
            *(float4*)&Ps[k * 64 + 4 * (ty ^ (k & 15))] = pv;
        }
        {
            const int lr2 = tid >> 4;
            const int lc2 = (tid & 15) * 4;
            #pragma unroll
            for (int rr = 0; rr < 4; rr++) {
                int k = lr2 + rr * 16;
                *(float4*)&KVs[k * 64 + lc2] =
                    *(const float4*)&Vg[(size_t)(k0 + k) * HDIM + lc2];
            }
        }
        __syncthreads();

        // ---- O += P V : outer product over k, acc packed over d-pairs ----
        #pragma unroll 8
        for (int k = 0; k < 64; k++) {
            float4 av = *(const float4*)&Ps[k * 64 + 4 * (ty ^ (k & 15))];
            ulonglong2 bu = *(const ulonglong2*)&KVs[k * 64 + tx * 4];
            unsigned long long a0 = pack2(av.x, av.x);
            unsigned long long a1 = pack2(av.y, av.y);
            unsigned long long a2 = pack2(av.z, av.z);
            unsigned long long a3 = pack2(av.w, av.w);
            ffma2(o2[0][0], a0, bu.x); ffma2(o2[0][1], a0, bu.y);
            ffma2(o2[1][0], a1, bu.x); ffma2(o2[1][1], a1, bu.y);
            ffma2(o2[2][0], a2, bu.x); ffma2(o2[2][1], a2, bu.y);
            ffma2(o2[3][0], a3, bu.x); ffma2(o2[3][1], a3, bu.y);
        }
    }

    // ---- epilogue: normalize and store [b][n][c], c = h*64 + d ----
    #pragma unroll
    for (int i = 0; i < 4; i++) {
        float inv = 1.0f / l_i[i];
        float o0, o1, o2f, o3;
        unpack2(o2[i][0], o0, o1);
        unpack2(o2[i][1], o2f, o3);
        float4 v;
        v.x = o0 * inv; v.y = o1 * inv;
        v.z = o2f * inv; v.w = o3 * inv;
        *(float4*)&g_O[((size_t)(b * NTOK + q0 + ty * 4 + i)) * CDIM + h * 64 + tx * 4] = v;
    }
}

// ============================================================================
// Kernel 3: output projection.  y[b,co,n] = sum_c O[b,n,c]*wo[co,c] + bo[co]
// acc packed along n (pairs); Wos scalar reads are warp-broadcast.
// ============================================================================
__global__ void __launch_bounds__(256) out_proj_kernel(
    const float* __restrict__ wo, const float* __restrict__ bo,
    float* __restrict__ y)
{
    const int n0  = blockIdx.x * 64;
    const int co0 = blockIdx.y * 64;
    const int b   = blockIdx.z;

    __shared__ float Os[64][68];    // [c][n], pad 68 keeps rows 16B-aligned
    __shared__ float Wos[64][65];   // [co][c]

    const int tid = threadIdx.x;
    const int tx = tid & 15, ty = tid >> 4;
    const int lr = tid >> 4;
    const int lc = (tid & 15) * 4;

    // acc2[i][j2]: i = co (4), j2 = n-pair (2)
    unsigned long long acc2[4][2];
    #pragma unroll
    for (int i = 0; i < 4; i++) { acc2[i][0] = 0ull; acc2[i][1] = 0ull; }

    for (int c0 = 0; c0 < CDIM; c0 += 64) {
        #pragma unroll
        for (int rr = 0; rr < 4; rr++) {
            int n = lr + rr * 16;
            float4 v = *(const float4*)&g_O[((size_t)(b * NTOK + n0 + n)) * CDIM + c0 + lc];
            Os[lc + 0][n] = v.x; Os[lc + 1][n] = v.y;
            Os[lc + 2][n] = v.z; Os[lc + 3][n] = v.w;
        }
        #pragma unroll
        for (int rr = 0; rr < 4; rr++) {
            int co = lr + rr * 16;
            float4 v = *(const float4*)&wo[(size_t)(co0 + co) * CDIM + c0 + lc];
            Wos[co][lc + 0] = v.x; Wos[co][lc + 1] = v.y;
            Wos[co][lc + 2] = v.z; Wos[co][lc + 3] = v.w;
        }
        __syncthreads();

        #pragma unroll 8
        for (int c = 0; c < 64; c++) {
            ulonglong2 bu = *(const ulonglong2*)&Os[c][tx * 4];   // n pairs
            #pragma unroll
            for (int i = 0; i < 4; i++) {
                float a = Wos[ty * 4 + i][c];
                unsigned long long ad = pack2(a, a);
                ffma2(acc2[i][0], ad, bu.x);
                ffma2(acc2[i][1], ad, bu.y);
            }
        }
        __syncthreads();
    }

    #pragma unroll
    for (int i = 0; i < 4; i++) {
        int co = co0 + ty * 4 + i;
        float bbias = bo[co];
        float a0, a1, a2f, a3;
        unpack2(acc2[i][0], a0, a1);
        unpack2(acc2[i][1], a2f, a3);
        float4 v;
        v.x = a0 + bbias; v.y = a1 + bbias;
        v.z = a2f + bbias; v.w = a3 + bbias;
        *(float4*)&y[((size_t)(b * CDIM + co)) * NTOK + n0 + tx * 4] = v;
    }
}

// ============================================================================
// Launch
// ============================================================================
extern "C" void kernel_launch(void* const* d_in, const int* in_sizes, int n_in,
                              void* d_out, int out_size)
{
    const float* x    = (const float*)d_in[0];
    const int*   mask = (const int*)d_in[1];   // numpy bool serialized as int32
    const float* wq   = (const float*)d_in[2];
    const float* bq   = (const float*)d_in[3];
    const float* wk   = (const float*)d_in[4];
    const float* bk   = (const float*)d_in[5];
    const float* wv   = (const float*)d_in[6];
    const float* bv   = (const float*)d_in[7];
    const float* wo   = (const float*)d_in[8];
    const float* bo   = (const float*)d_in[9];
    float* y = (float*)d_out;

    qkv_proj_kernel<<<dim3(NTOK / 64, 12, BATCH), 256>>>(x, wq, bq, wk, bk, wv, bv);
    attn_kernel<<<dim3(NTOK / 64, BHDIM), 256>>>(mask);
    out_proj_kernel<<<dim3(NTOK / 64, CDIM / 64, BATCH), 256>>>(wo, bo, y);
}

// round 5
// speedup vs baseline: 1.2190x; 1.0578x over previous
#include <cuda_runtime.h>
#include <math.h>

#define BATCH  2
#define CDIM   256
#define NHEADS 4
#define HDIM   64
#define NTOK   4096
#define BHDIM  (BATCH * NHEADS)

// ---- scratch (static device globals: no runtime allocation) ----
__device__ float g_Q[BHDIM * NTOK * HDIM];   // [b,h,n,d]  8 MB
__device__ float g_K[BHDIM * NTOK * HDIM];   // 8 MB
__device__ float g_V[BHDIM * NTOK * HDIM];   // 8 MB
__device__ float g_O[BATCH * NTOK * CDIM];   // [b,n,c] c = h*64+d, 8 MB

// ---- packed fp32x2 helpers (sm_100+: f32x2 ops on 64-bit register pairs) ----
__device__ __forceinline__ unsigned long long pack2(float lo, float hi) {
    unsigned long long r;
    asm("mov.b64 %0, {%1, %2};" : "=l"(r) : "f"(lo), "f"(hi));
    return r;
}
__device__ __forceinline__ void unpack2(unsigned long long v, float& lo, float& hi) {
    asm("mov.b64 {%0, %1}, %2;" : "=f"(lo), "=f"(hi) : "l"(v));
}
__device__ __forceinline__ void ffma2(unsigned long long& d,
                                      unsigned long long a, unsigned long long b) {
    asm("fma.rn.f32x2 %0, %1, %2, %0;" : "+l"(d) : "l"(a), "l"(b));
}
__device__ __forceinline__ void fmul2(unsigned long long& d, unsigned long long a) {
    asm("mul.rn.f32x2 %0, %0, %1;" : "+l"(d) : "l"(a));
}
__device__ __forceinline__ void fadd2(unsigned long long& d, unsigned long long a) {
    asm("add.rn.f32x2 %0, %0, %1;" : "+l"(d) : "l"(a));
}

// ============================================================================
// Kernel 1: QKV projection (unchanged, verified).
// ============================================================================
__global__ void __launch_bounds__(256) qkv_proj_kernel(
    const float* __restrict__ x,
    const float* __restrict__ wq, const float* __restrict__ bq,
    const float* __restrict__ wk, const float* __restrict__ bk,
    const float* __restrict__ wv, const float* __restrict__ bv)
{
    const int n0    = blockIdx.x * 64;
    const int which = blockIdx.y >> 2;
    const int co0   = (blockIdx.y & 3) * 64;
    const int b     = blockIdx.z;

    const float* w; const float* bias; float* out;
    if (which == 0)      { w = wq; bias = bq; out = g_Q; }
    else if (which == 1) { w = wk; bias = bk; out = g_K; }
    else                 { w = wv; bias = bv; out = g_V; }

    __shared__ float Xs[64][64];
    __shared__ float Ws[64][65];

    const int tid = threadIdx.x;
    const int tx = tid & 15, ty = tid >> 4;
    const int lr = tid >> 4;
    const int lc = (tid & 15) * 4;

    unsigned long long acc2[4][2];
    #pragma unroll
    for (int j = 0; j < 4; j++) { acc2[j][0] = 0ull; acc2[j][1] = 0ull; }

    for (int c0 = 0; c0 < CDIM; c0 += 64) {
        #pragma unroll
        for (int rr = 0; rr < 4; rr++) {
            int c = lr + rr * 16;
            float4 v = *(const float4*)&x[(size_t)(b * CDIM + c0 + c) * NTOK + n0 + lc];
            *(float4*)&Xs[c][lc] = v;
        }
        #pragma unroll
        for (int rr = 0; rr < 4; rr++) {
            int co = lr + rr * 16;
            float4 v = *(const float4*)&w[(size_t)(co0 + co) * CDIM + c0 + lc];
            Ws[co][lc + 0] = v.x; Ws[co][lc + 1] = v.y;
            Ws[co][lc + 2] = v.z; Ws[co][lc + 3] = v.w;
        }
        __syncthreads();

        #pragma unroll 8
        for (int c = 0; c < 64; c++) {
            ulonglong2 au = *(const ulonglong2*)&Xs[c][ty * 4];
            #pragma unroll
            for (int j = 0; j < 4; j++) {
                float bb = Ws[tx * 4 + j][c];
                unsigned long long bd = pack2(bb, bb);
                ffma2(acc2[j][0], bd, au.x);
                ffma2(acc2[j][1], bd, au.y);
            }
        }
        __syncthreads();
    }

    float accf[4][4];
    #pragma unroll
    for (int j = 0; j < 4; j++) {
        unpack2(acc2[j][0], accf[0][j], accf[1][j]);
        unpack2(acc2[j][1], accf[2][j], accf[3][j]);
    }

    const int h = co0 >> 6;
    #pragma unroll
    for (int i = 0; i < 4; i++) {
        int n = n0 + ty * 4 + i;
        float4 v;
        v.x = accf[i][0] + bias[co0 + tx * 4 + 0];
        v.y = accf[i][1] + bias[co0 + tx * 4 + 1];
        v.z = accf[i][2] + bias[co0 + tx * 4 + 2];
        v.w = accf[i][3] + bias[co0 + tx * 4 + 3];
        *(float4*)&out[((size_t)(b * NHEADS + h) * NTOK + n) * HDIM + tx * 4] = v;
    }
}

// ============================================================================
// Kernel 2: masked flash attention, 128x128 block tile, 8x8 thread tile,
// FFMA2 GEMMs at 2 FLOP/LDS-byte. 128KB dynamic smem, 1 CTA/SM.
//   Qs [64 d][128 q]   chunk-swizzled: chunk' = ch ^ (d&31)
//   KV [64 d][128 k] (K phase) / [128 k][64 d] (V phase, swz ch ^ (k&15))
//   Ps [128 k][128 q]  swizzled: chunk' = ch ^ rot(k), rot = ((k&3)<<3)|((k>>2)&7)
// Thread (ty=tid>>4, tx=tid&15): S tile rows q=8ty.., cols k=4tx..+3 & 64+4tx..+3.
// PV: split-K in-warp: g=tx&7 -> d group, tx>>3 -> k half; combined via shfl.
// ============================================================================
__global__ void __launch_bounds__(256, 1) attn_kernel(const int* __restrict__ mask)
{
    extern __shared__ float sm[];
    float* Qs = sm;                 // 64*128
    float* KV = sm + 64 * 128;      // 64*128 (K) aliased with 128*64 (V)
    float* Ps = sm + 2 * 64 * 128;  // 128*128

    const int q0 = blockIdx.x * 128;
    const int bh = blockIdx.y;
    const int b  = bh >> 2;
    const int h  = bh & 3;

    const float* __restrict__ Qg = g_Q + (size_t)bh * NTOK * HDIM;
    const float* __restrict__ Kg = g_K + (size_t)bh * NTOK * HDIM;
    const float* __restrict__ Vg = g_V + (size_t)bh * NTOK * HDIM;

    const int tid = threadIdx.x;
    const int tx  = tid & 15, ty = tid >> 4;
    const int d64 = tid & 63, cb = tid >> 6;

    // ---- load Q tile transposed [d][q], swizzled ----
    #pragma unroll
    for (int it = 0; it < 8; it++) {
        int ch = cb * 8 + it;               // q-chunk 0..31
        float4 v;
        v.x = Qg[(size_t)(q0 + ch * 4 + 0) * HDIM + d64];
        v.y = Qg[(size_t)(q0 + ch * 4 + 1) * HDIM + d64];
        v.z = Qg[(size_t)(q0 + ch * 4 + 2) * HDIM + d64];
        v.w = Qg[(size_t)(q0 + ch * 4 + 3) * HDIM + d64];
        *(float4*)&Qs[d64 * 128 + 4 * (ch ^ (d64 & 31))] = v;
    }

    float m_i[8], l_i[8];
    unsigned long long o2[8][4];
    #pragma unroll
    for (int i = 0; i < 8; i++) {
        m_i[i] = -INFINITY; l_i[i] = 0.0f;
        #pragma unroll
        for (int j = 0; j < 4; j++) o2[i][j] = 0ull;
    }

    const float scale = 0.125f;
    const size_t mbase = (size_t)b * NTOK * NTOK;

    for (int kt = 0; kt < NTOK / 128; kt++) {
        const int k0 = kt * 128;

        __syncthreads();                    // prior PV / Q-load done
        // ---- K tile -> KV as [d][k], swizzled ----
        #pragma unroll
        for (int it = 0; it < 8; it++) {
            int ch = cb * 8 + it;
            float4 v;
            v.x = Kg[(size_t)(k0 + ch * 4 + 0) * HDIM + d64];
            v.y = Kg[(size_t)(k0 + ch * 4 + 1) * HDIM + d64];
            v.z = Kg[(size_t)(k0 + ch * 4 + 2) * HDIM + d64];
            v.w = Kg[(size_t)(k0 + ch * 4 + 3) * HDIM + d64];
            *(float4*)&KV[d64 * 128 + 4 * (ch ^ (d64 & 31))] = v;
        }
        __syncthreads();

        // ---- S = Q K^T over d (8q x 8k per thread) ----
        unsigned long long s2[8][4];
        #pragma unroll
        for (int i = 0; i < 8; i++)
            #pragma unroll
            for (int j = 0; j < 4; j++) s2[i][j] = 0ull;

        #pragma unroll 8
        for (int d = 0; d < 64; d++) {
            const int e = d & 31;
            float4 qa = *(const float4*)&Qs[d * 128 + 4 * ((2 * ty) ^ e)];
            float4 qb = *(const float4*)&Qs[d * 128 + 4 * ((2 * ty + 1) ^ e)];
            ulonglong2 k1 = *(const ulonglong2*)&KV[d * 128 + 4 * (tx ^ e)];
            ulonglong2 k2 = *(const ulonglong2*)&KV[d * 128 + 4 * ((tx ^ 16) ^ e)];
            float qv[8] = {qa.x, qa.y, qa.z, qa.w, qb.x, qb.y, qb.z, qb.w};
            #pragma unroll
            for (int i = 0; i < 8; i++) {
                unsigned long long a = pack2(qv[i], qv[i]);
                ffma2(s2[i][0], a, k1.x);
                ffma2(s2[i][1], a, k1.y);
                ffma2(s2[i][2], a, k2.x);
                ffma2(s2[i][3], a, k2.y);
            }
        }

        float s[8][8];
        #pragma unroll
        for (int i = 0; i < 8; i++) {
            unpack2(s2[i][0], s[i][0], s[i][1]);
            unpack2(s2[i][1], s[i][2], s[i][3]);
            unpack2(s2[i][2], s[i][4], s[i][5]);
            unpack2(s2[i][3], s[i][6], s[i][7]);
        }

        // ---- mask + scale + online softmax (rows reduce over 16 lanes) ----
        #pragma unroll
        for (int i = 0; i < 8; i++) {
            const size_t roff = mbase + (size_t)(q0 + ty * 8 + i) * NTOK + k0;
            const int4 m1 = *(const int4*)(mask + roff + 4 * tx);
            const int4 m2 = *(const int4*)(mask + roff + 64 + 4 * tx);
            s[i][0] = m1.x ? s[i][0] * scale : -INFINITY;
            s[i][1] = m1.y ? s[i][1] * scale : -INFINITY;
            s[i][2] = m1.z ? s[i][2] * scale : -INFINITY;
            s[i][3] = m1.w ? s[i][3] * scale : -INFINITY;
            s[i][4] = m2.x ? s[i][4] * scale : -INFINITY;
            s[i][5] = m2.y ? s[i][5] * scale : -INFINITY;
            s[i][6] = m2.z ? s[i][6] * scale : -INFINITY;
            s[i][7] = m2.w ? s[i][7] * scale : -INFINITY;

            float tm = s[i][0];
            #pragma unroll
            for (int j = 1; j < 8; j++) tm = fmaxf(tm, s[i][j]);
            #pragma unroll
            for (int off = 1; off < 16; off <<= 1)
                tm = fmaxf(tm, __shfl_xor_sync(0xffffffffu, tm, off));

            float mn = fmaxf(m_i[i], tm);
            float alpha = (mn == -INFINITY) ? 1.0f : __expf(m_i[i] - mn);

            float rs = 0.0f;
            #pragma unroll
            for (int j = 0; j < 8; j++) {
                float p = (s[i][j] == -INFINITY) ? 0.0f : __expf(s[i][j] - mn);
                s[i][j] = p;
                rs += p;
            }
            #pragma unroll
            for (int off = 1; off < 16; off <<= 1)
                rs += __shfl_xor_sync(0xffffffffu, rs, off);

            l_i[i] = l_i[i] * alpha + rs;
            m_i[i] = mn;
            unsigned long long ad = pack2(alpha, alpha);
            #pragma unroll
            for (int j = 0; j < 4; j++) fmul2(o2[i][j], ad);
        }

        __syncthreads();                    // S reads of KV done
        // ---- store P^T [k][q] swizzled ----
        #pragma unroll
        for (int j = 0; j < 4; j++) {
            const int rot = (j << 3) | (tx & 7);
            const int ka = 4 * tx + j;
            const int kb = 64 + 4 * tx + j;
            float4 p;
            p.x = s[0][j]; p.y = s[1][j]; p.z = s[2][j]; p.w = s[3][j];
            *(float4*)&Ps[ka * 128 + 4 * ((2 * ty) ^ rot)] = p;
            p.x = s[4][j]; p.y = s[5][j]; p.z = s[6][j]; p.w = s[7][j];
            *(float4*)&Ps[ka * 128 + 4 * ((2 * ty + 1) ^ rot)] = p;
            p.x = s[0][4 + j]; p.y = s[1][4 + j]; p.z = s[2][4 + j]; p.w = s[3][4 + j];
            *(float4*)&Ps[kb * 128 + 4 * ((2 * ty) ^ rot)] = p;
            p.x = s[4][4 + j]; p.y = s[5][4 + j]; p.z = s[6][4 + j]; p.w = s[7][4 + j];
            *(float4*)&Ps[kb * 128 + 4 * ((2 * ty + 1) ^ rot)] = p;
        }
        // ---- V tile -> KV as [k][d], swizzled (coalesced linear copy) ----
        #pragma unroll
        for (int it = 0; it < 8; it++) {
            int idx = tid + it * 256;       // 0..2047 float4s
            int k   = idx >> 4;
            int ch  = idx & 15;
            float4 v = *(const float4*)&Vg[(size_t)k0 * HDIM + idx * 4];
            *(float4*)&KV[k * 64 + 4 * (ch ^ (k & 15))] = v;
        }
        __syncthreads();

        // ---- O += P V over k (split-K: lane half tx>>3) ----
        {
            const int g = tx & 7;
            const int khalf = (tx >> 3) * 64;
            #pragma unroll 8
            for (int kk = 0; kk < 64; kk++) {
                const int krow = khalf + kk;
                const int rot = ((krow & 3) << 3) | ((krow >> 2) & 7);
                float4 pa = *(const float4*)&Ps[krow * 128 + 4 * ((2 * ty) ^ rot)];
                float4 pb = *(const float4*)&Ps[krow * 128 + 4 * ((2 * ty + 1) ^ rot)];
                const int e2 = krow & 15;
                ulonglong2 v1 = *(const ulonglong2*)&KV[krow * 64 + 4 * (g ^ e2)];
                ulonglong2 v2 = *(const ulonglong2*)&KV[krow * 64 + 4 * ((g ^ 8) ^ e2)];
                float pv[8] = {pa.x, pa.y, pa.z, pa.w, pb.x, pb.y, pb.z, pb.w};
                #pragma unroll
                for (int i = 0; i < 8; i++) {
                    unsigned long long a = pack2(pv[i], pv[i]);
                    ffma2(o2[i][0], a, v1.x);
                    ffma2(o2[i][1], a, v1.y);
                    ffma2(o2[i][2], a, v2.x);
                    ffma2(o2[i][3], a, v2.y);
                }
            }
        }
    }

    // ---- combine split-K halves (lane ^ 8 within warp) ----
    #pragma unroll
    for (int i = 0; i < 8; i++)
        #pragma unroll
        for (int j = 0; j < 4; j++) {
            unsigned long long other = __shfl_xor_sync(0xffffffffu, o2[i][j], 8);
            fadd2(o2[i][j], other);
        }

    // ---- epilogue: normalize, store [b][n][c], c = h*64 + d ----
    if ((tx & 8) == 0) {
        const int g = tx & 7;
        #pragma unroll
        for (int i = 0; i < 8; i++) {
            float inv = 1.0f / l_i[i];
            float f[8];
            unpack2(o2[i][0], f[0], f[1]);
            unpack2(o2[i][1], f[2], f[3]);
            unpack2(o2[i][2], f[4], f[5]);
            unpack2(o2[i][3], f[6], f[7]);
            float* dst = &g_O[((size_t)(b * NTOK + q0 + ty * 8 + i)) * CDIM + h * 64];
            float4 v;
            v.x = f[0] * inv; v.y = f[1] * inv; v.z = f[2] * inv; v.w = f[3] * inv;
            *(float4*)&dst[4 * g] = v;
            v.x = f[4] * inv; v.y = f[5] * inv; v.z = f[6] * inv; v.w = f[7] * inv;
            *(float4*)&dst[32 + 4 * g] = v;
        }
    }
}

// ============================================================================
// Kernel 3: output projection (unchanged, verified).
// ============================================================================
__global__ void __launch_bounds__(256) out_proj_kernel(
    const float* __restrict__ wo, const float* __restrict__ bo,
    float* __restrict__ y)
{
    const int n0  = blockIdx.x * 64;
    const int co0 = blockIdx.y * 64;
    const int b   = blockIdx.z;

    __shared__ float Os[64][68];
    __shared__ float Wos[64][65];

    const int tid = threadIdx.x;
    const int tx = tid & 15, ty = tid >> 4;
    const int lr = tid >> 4;
    const int lc = (tid & 15) * 4;

    unsigned long long acc2[4][2];
    #pragma unroll
    for (int i = 0; i < 4; i++) { acc2[i][0] = 0ull; acc2[i][1] = 0ull; }

    for (int c0 = 0; c0 < CDIM; c0 += 64) {
        #pragma unroll
        for (int rr = 0; rr < 4; rr++) {
            int n = lr + rr * 16;
            float4 v = *(const float4*)&g_O[((size_t)(b * NTOK + n0 + n)) * CDIM + c0 + lc];
            Os[lc + 0][n] = v.x; Os[lc + 1][n] = v.y;
            Os[lc + 2][n] = v.z; Os[lc + 3][n] = v.w;
        }
        #pragma unroll
        for (int rr = 0; rr < 4; rr++) {
            int co = lr + rr * 16;
            float4 v = *(const float4*)&wo[(size_t)(co0 + co) * CDIM + c0 + lc];
            Wos[co][lc + 0] = v.x; Wos[co][lc + 1] = v.y;
            Wos[co][lc + 2] = v.z; Wos[co][lc + 3] = v.w;
        }
        __syncthreads();

        #pragma unroll 8
        for (int c = 0; c < 64; c++) {
            ulonglong2 bu = *(const ulonglong2*)&Os[c][tx * 4];
            #pragma unroll
            for (int i = 0; i < 4; i++) {
                float a = Wos[ty * 4 + i][c];
                unsigned long long ad = pack2(a, a);
                ffma2(acc2[i][0], ad, bu.x);
                ffma2(acc2[i][1], ad, bu.y);
            }
        }
        __syncthreads();
    }

    #pragma unroll
    for (int i = 0; i < 4; i++) {
        int co = co0 + ty * 4 + i;
        float bbias = bo[co];
        float a0, a1, a2f, a3;
        unpack2(acc2[i][0], a0, a1);
        unpack2(acc2[i][1], a2f, a3);
        float4 v;
        v.x = a0 + bbias; v.y = a1 + bbias;
        v.z = a2f + bbias; v.w = a3 + bbias;
        *(float4*)&y[((size_t)(b * CDIM + co)) * NTOK + n0 + tx * 4] = v;
    }
}

// ============================================================================
// Launch
// ============================================================================
extern "C" void kernel_launch(void* const* d_in, const int* in_sizes, int n_in,
                              void* d_out, int out_size)
{
    const float* x    = (const float*)d_in[0];
    const int*   mask = (const int*)d_in[1];   // numpy bool serialized as int32
    const float* wq   = (const float*)d_in[2];
    const float* bq   = (const float*)d_in[3];
    const float* wk   = (const float*)d_in[4];
    const float* bk   = (const float*)d_in[5];
    const float* wv   = (const float*)d_in[6];
    const float* bv   = (const float*)d_in[7];
    const float* wo   = (const float*)d_in[8];
    const float* bo   = (const float*)d_in[9];
    float* y = (float*)d_out;

    const int ATTN_SMEM = 128 * 1024;   // Qs 32KB + KV 32KB + Ps 64KB
    cudaFuncSetAttribute(attn_kernel,
                         cudaFuncAttributeMaxDynamicSharedMemorySize, ATTN_SMEM);

    qkv_proj_kernel<<<dim3(NTOK / 64, 12, BATCH), 256>>>(x, wq, bq, wk, bk, wv, bv);
    attn_kernel<<<dim3(NTOK / 128, BHDIM), 256, ATTN_SMEM>>>(mask);
    out_proj_kernel<<<dim3(NTOK / 64, CDIM / 64, BATCH), 256>>>(wo, bo, y);
}

// round 7
// speedup vs baseline: 2.8440x; 2.3330x over previous
#include <cuda_runtime.h>
#include <cuda_bf16.h>
#include <math.h>
#include <stdint.h>

#define BATCH  2
#define CDIM   256
#define NHEADS 4
#define HDIM   64
#define NTOK   4096
#define BHDIM  (BATCH * NHEADS)
#define KTILES (NTOK / 128)

// ---- scratch (static device globals) ----
// bf16 hi/lo splits of Q,K,V in ldmatrix-ready layout: [bh][token][64d],
// 128B rows, 16B chunks XOR-swizzled by (row & 7).
__device__ __nv_bfloat16 g_Qh[BHDIM * NTOK * HDIM];
__device__ __nv_bfloat16 g_Ql[BHDIM * NTOK * HDIM];
__device__ __nv_bfloat16 g_Kh[BHDIM * NTOK * HDIM];
__device__ __nv_bfloat16 g_Kl[BHDIM * NTOK * HDIM];
__device__ __nv_bfloat16 g_Vh[BHDIM * NTOK * HDIM];
__device__ __nv_bfloat16 g_Vl[BHDIM * NTOK * HDIM];
__device__ float g_O[BATCH * NTOK * CDIM];   // [b][n][c], c = h*64+d

// ---- packed fp32x2 helpers (for SIMT projection kernels) ----
__device__ __forceinline__ unsigned long long pack2(float lo, float hi) {
    unsigned long long r;
    asm("mov.b64 %0, {%1, %2};" : "=l"(r) : "f"(lo), "f"(hi));
    return r;
}
__device__ __forceinline__ void unpack2(unsigned long long v, float& lo, float& hi) {
    asm("mov.b64 {%0, %1}, %2;" : "=f"(lo), "=f"(hi) : "l"(v));
}
__device__ __forceinline__ void ffma2(unsigned long long& d, unsigned long long a, unsigned long long b) {
    asm("fma.rn.f32x2 %0, %1, %2, %0;" : "+l"(d) : "l"(a), "l"(b));
}

// ---- mma.sync / ldmatrix / cp.async helpers ----
__device__ __forceinline__ uint32_t smem_u32(const void* p) {
    uint32_t a;
    asm("{ .reg .u64 t; cvta.to.shared.u64 t, %1; cvt.u32.u64 %0, t; }" : "=r"(a) : "l"(p));
    return a;
}
__device__ __forceinline__ void mma16816(float* c, const uint32_t* a, uint32_t b0, uint32_t b1) {
    asm volatile("mma.sync.aligned.m16n8k16.row.col.f32.bf16.bf16.f32 "
        "{%0,%1,%2,%3}, {%4,%5,%6,%7}, {%8,%9}, {%0,%1,%2,%3};"
        : "+f"(c[0]), "+f"(c[1]), "+f"(c[2]), "+f"(c[3])
        : "r"(a[0]), "r"(a[1]), "r"(a[2]), "r"(a[3]), "r"(b0), "r"(b1));
}
__device__ __forceinline__ void ldsm4(uint32_t* r, uint32_t a) {
    asm volatile("ldmatrix.sync.aligned.m8n8.x4.shared.b16 {%0,%1,%2,%3}, [%4];"
        : "=r"(r[0]), "=r"(r[1]), "=r"(r[2]), "=r"(r[3]) : "r"(a));
}
__device__ __forceinline__ void ldsm4t(uint32_t* r, uint32_t a) {
    asm volatile("ldmatrix.sync.aligned.m8n8.x4.trans.shared.b16 {%0,%1,%2,%3}, [%4];"
        : "=r"(r[0]), "=r"(r[1]), "=r"(r[2]), "=r"(r[3]) : "r"(a));
}
__device__ __forceinline__ void cp16(uint32_t s, const void* g) {
    asm volatile("cp.async.cg.shared.global [%0], [%1], 16;" :: "r"(s), "l"(g) : "memory");
}
#define CP_COMMIT() asm volatile("cp.async.commit_group;" ::: "memory")
#define CP_WAIT(n)  asm volatile("cp.async.wait_group %0;" :: "n"(n) : "memory")

__device__ __forceinline__ float ex2f(float x) {
    float r; asm("ex2.approx.f32 %0, %1;" : "=f"(r) : "f"(x)); return r;
}
__device__ __forceinline__ uint32_t bf2_u32(__nv_bfloat162 v) {
    return *reinterpret_cast<uint32_t*>(&v);
}
// swizzled smem address: 128B rows, 16B chunks, chunk ^= (row & 7)
__device__ __forceinline__ uint32_t swa(uint32_t base, int row, int chunk) {
    return base + (row << 7) + (((chunk ^ (row & 7))) << 4);
}

// ============================================================================
// Kernel 1: QKV projection -> bf16 hi/lo split, swizzled rows.
// ============================================================================
__global__ void __launch_bounds__(256) qkv_proj_kernel(
    const float* __restrict__ x,
    const float* __restrict__ wq, const float* __restrict__ bq,
    const float* __restrict__ wk, const float* __restrict__ bk,
    const float* __restrict__ wv, const float* __restrict__ bv)
{
    const int n0    = blockIdx.x * 64;
    const int which = blockIdx.y >> 2;
    const int co0   = (blockIdx.y & 3) * 64;
    const int b     = blockIdx.z;

    const float* w; const float* bias;
    __nv_bfloat16* oh; __nv_bfloat16* ol;
    if (which == 0)      { w = wq; bias = bq; oh = g_Qh; ol = g_Ql; }
    else if (which == 1) { w = wk; bias = bk; oh = g_Kh; ol = g_Kl; }
    else                 { w = wv; bias = bv; oh = g_Vh; ol = g_Vl; }

    __shared__ float Xs[64][64];
    __shared__ float Ws[64][65];

    const int tid = threadIdx.x;
    const int tx = tid & 15, ty = tid >> 4;
    const int lr = tid >> 4;
    const int lc = (tid & 15) * 4;

    unsigned long long acc2[4][2];
    #pragma unroll
    for (int j = 0; j < 4; j++) { acc2[j][0] = 0ull; acc2[j][1] = 0ull; }

    for (int c0 = 0; c0 < CDIM; c0 += 64) {
        #pragma unroll
        for (int rr = 0; rr < 4; rr++) {
            int c = lr + rr * 16;
            float4 v = *(const float4*)&x[(size_t)(b * CDIM + c0 + c) * NTOK + n0 + lc];
            *(float4*)&Xs[c][lc] = v;
        }
        #pragma unroll
        for (int rr = 0; rr < 4; rr++) {
            int co = lr + rr * 16;
            float4 v = *(const float4*)&w[(size_t)(co0 + co) * CDIM + c0 + lc];
            Ws[co][lc + 0] = v.x; Ws[co][lc + 1] = v.y;
            Ws[co][lc + 2] = v.z; Ws[co][lc + 3] = v.w;
        }
        __syncthreads();

        #pragma unroll 8
        for (int c = 0; c < 64; c++) {
            ulonglong2 au = *(const ulonglong2*)&Xs[c][ty * 4];
            #pragma unroll
            for (int j = 0; j < 4; j++) {
                float bb = Ws[tx * 4 + j][c];
                unsigned long long bd = pack2(bb, bb);
                ffma2(acc2[j][0], bd, au.x);
                ffma2(acc2[j][1], bd, au.y);
            }
        }
        __syncthreads();
    }

    float accf[4][4];
    #pragma unroll
    for (int j = 0; j < 4; j++) {
        unpack2(acc2[j][0], accf[0][j], accf[1][j]);
        unpack2(acc2[j][1], accf[2][j], accf[3][j]);
    }

    const int h = co0 >> 6;
    const size_t rowbase = (size_t)(b * NHEADS + h) * NTOK;
    #pragma unroll
    for (int i = 0; i < 4; i++) {
        int n = n0 + ty * 4 + i;
        float v0 = accf[i][0] + bias[co0 + tx * 4 + 0];
        float v1 = accf[i][1] + bias[co0 + tx * 4 + 1];
        float v2 = accf[i][2] + bias[co0 + tx * 4 + 2];
        float v3 = accf[i][3] + bias[co0 + tx * 4 + 3];
        __nv_bfloat162 h01 = __floats2bfloat162_rn(v0, v1);
        __nv_bfloat162 h23 = __floats2bfloat162_rn(v2, v3);
        __nv_bfloat162 l01 = __floats2bfloat162_rn(v0 - __low2float(h01), v1 - __high2float(h01));
        __nv_bfloat162 l23 = __floats2bfloat162_rn(v2 - __low2float(h23), v3 - __high2float(h23));
        size_t byteoff = (rowbase + n) * 128 + (size_t)((((tx >> 1) ^ (n & 7)) << 4) + ((tx & 1) << 3));
        uint2 hv; hv.x = bf2_u32(h01); hv.y = bf2_u32(h23);
        uint2 lv; lv.x = bf2_u32(l01); lv.y = bf2_u32(l23);
        *(uint2*)((char*)oh + byteoff) = hv;
        *(uint2*)((char*)ol + byteoff) = lv;
    }
}

// ============================================================================
// Kernel 2: flash attention via mma.sync m16n8k16 bf16 (hi/lo split).
// CTA: 128 q rows, 8 warps x 16 rows. Per k-tile (128 keys):
//   S(16x128/warp) = Q Kt (3-way split), fixed-shift softmax, O += P V.
// cp.async double-buffered K/V smem tiles; Q frags register-resident.
// ============================================================================
#define SCLOG2 0.18033688f      /* 0.125 * log2(e) */
#define SHLOG2 (-11.54156003f)  /* -8    * log2(e) */

// smem: Qh 16K | Ql 16K | buf0: Kh,Kl,Vh,Vl 16K each | buf1: same
#define SM_Q    0
#define SM_BUF  32768
#define SM_BUFSZ 65536
#define ATTN_SMEM (32768 + 2 * SM_BUFSZ)

__device__ __forceinline__ void copy_tile(uint32_t dst, const char* kh, const char* kl,
                                          const char* vh, const char* vl, int tid)
{
    #pragma unroll
    for (int j = 0; j < 4; j++) {
        uint32_t o = (uint32_t)(tid + j * 256) * 16;
        cp16(dst +         o, kh + o);
        cp16(dst + 16384 + o, kl + o);
        cp16(dst + 32768 + o, vh + o);
        cp16(dst + 49152 + o, vl + o);
    }
}

__global__ void __launch_bounds__(256, 1) attn_kernel(const int* __restrict__ mask)
{
    extern __shared__ char smem[];
    const uint32_t sb = smem_u32(smem);
    const int tid = threadIdx.x;
    const int w = tid >> 5, L = tid & 31;
    const int gr = L >> 2, tc = L & 3;

    const int q0 = blockIdx.x * 128;
    const int bh = blockIdx.y;
    const int b = bh >> 2, h = bh & 3;

    const size_t tb2 = (size_t)bh * NTOK * HDIM * 2;   // byte base of this head

    const char* qh_g = (const char*)g_Qh + tb2 + (size_t)q0 * 128;
    const char* ql_g = (const char*)g_Ql + tb2 + (size_t)q0 * 128;
    const char* kh_g = (const char*)g_Kh + tb2;
    const char* kl_g = (const char*)g_Kl + tb2;
    const char* vh_g = (const char*)g_Vh + tb2;
    const char* vl_g = (const char*)g_Vl + tb2;

    // prologue: Q + tile0 (group 1), tile1 (group 2)
    #pragma unroll
    for (int j = 0; j < 4; j++) {
        uint32_t o = (uint32_t)(tid + j * 256) * 16;
        cp16(sb + SM_Q + o,         qh_g + o);
        cp16(sb + SM_Q + 16384 + o, ql_g + o);
    }
    copy_tile(sb + SM_BUF, kh_g, kl_g, vh_g, vl_g, tid);
    CP_COMMIT();
    copy_tile(sb + SM_BUF + SM_BUFSZ, kh_g + 16384, kl_g + 16384, vh_g + 16384, vl_g + 16384, tid);
    CP_COMMIT();
    CP_WAIT(1);
    __syncthreads();

    // Q fragments (A of m16n8k16): rows w*16 .. w*16+15
    uint32_t qh[4][4], ql[4][4];
    #pragma unroll
    for (int ks = 0; ks < 4; ks++) {
        int row = (w << 4) + (L & 7) + (((L >> 3) & 1) << 3);
        int ch  = 2 * ks + (L >> 4);
        ldsm4(qh[ks], swa(sb + SM_Q,         row, ch));
        ldsm4(ql[ks], swa(sb + SM_Q + 16384, row, ch));
    }

    float o[8][4];
    #pragma unroll
    for (int i = 0; i < 8; i++) { o[i][0] = o[i][1] = o[i][2] = o[i][3] = 0.0f; }
    float l0 = 0.0f, l1 = 0.0f;

    const int r0 = q0 + w * 16 + gr;
    const int2* m0p = (const int2*)(mask + (size_t)b * NTOK * NTOK + (size_t)r0 * NTOK);
    const int2* m1p = (const int2*)(mask + (size_t)b * NTOK * NTOK + (size_t)(r0 + 8) * NTOK);

    for (int t = 0; t < KTILES; t++) {
        const uint32_t kb = sb + SM_BUF + (t & 1) * SM_BUFSZ;

        // ---- S = Q K^T ----
        float s[16][4];
        #pragma unroll
        for (int n = 0; n < 16; n++) { s[n][0] = s[n][1] = s[n][2] = s[n][3] = 0.0f; }

        #pragma unroll
        for (int n = 0; n < 16; n++) {
            #pragma unroll
            for (int ksp = 0; ksp < 2; ksp++) {
                int row = 8 * n + (L & 7);
                int ch  = 4 * ksp + (L >> 3);
                uint32_t khf[4], klf[4];
                ldsm4(khf, swa(kb,         row, ch));
                ldsm4(klf, swa(kb + 16384, row, ch));
                mma16816(s[n], qh[2 * ksp],     khf[0], khf[1]);
                mma16816(s[n], qh[2 * ksp],     klf[0], klf[1]);
                mma16816(s[n], ql[2 * ksp],     khf[0], khf[1]);
                mma16816(s[n], qh[2 * ksp + 1], khf[2], khf[3]);
                mma16816(s[n], qh[2 * ksp + 1], klf[2], klf[3]);
                mma16816(s[n], ql[2 * ksp + 1], khf[2], khf[3]);
            }
        }

        // ---- fixed-shift softmax + P hi/lo frags ----
        uint32_t ph[16][2], pl[16][2];
        #pragma unroll
        for (int n = 0; n < 16; n++) {
            int midx = t * 64 + 4 * n + tc;
            int2 ma = m0p[midx];
            int2 mb = m1p[midx];
            float p0 = ma.x ? ex2f(fmaf(s[n][0], SCLOG2, SHLOG2)) : 0.0f;
            float p1 = ma.y ? ex2f(fmaf(s[n][1], SCLOG2, SHLOG2)) : 0.0f;
            float p2 = mb.x ? ex2f(fmaf(s[n][2], SCLOG2, SHLOG2)) : 0.0f;
            float p3 = mb.y ? ex2f(fmaf(s[n][3], SCLOG2, SHLOG2)) : 0.0f;
            l0 += p0 + p1;
            l1 += p2 + p3;
            __nv_bfloat162 h01 = __floats2bfloat162_rn(p0, p1);
            __nv_bfloat162 h23 = __floats2bfloat162_rn(p2, p3);
            __nv_bfloat162 e01 = __floats2bfloat162_rn(p0 - __low2float(h01), p1 - __high2float(h01));
            __nv_bfloat162 e23 = __floats2bfloat162_rn(p2 - __low2float(h23), p3 - __high2float(h23));
            ph[n][0] = bf2_u32(h01); ph[n][1] = bf2_u32(h23);
            pl[n][0] = bf2_u32(e01); pl[n][1] = bf2_u32(e23);
        }

        // ---- O += P V ----
        #pragma unroll
        for (int kp = 0; kp < 8; kp++) {
            uint32_t ah[4] = { ph[2 * kp][0], ph[2 * kp][1], ph[2 * kp + 1][0], ph[2 * kp + 1][1] };
            uint32_t al[4] = { pl[2 * kp][0], pl[2 * kp][1], pl[2 * kp + 1][0], pl[2 * kp + 1][1] };
            #pragma unroll
            for (int dp = 0; dp < 4; dp++) {
                int row = (kp << 4) + (L & 7) + (((L >> 3) & 1) << 3);
                int ch  = 2 * dp + (L >> 4);
                uint32_t vhf[4], vlf[4];
                ldsm4t(vhf, swa(kb + 32768, row, ch));
                ldsm4t(vlf, swa(kb + 49152, row, ch));
                mma16816(o[2 * dp],     ah, vhf[0], vhf[1]);
                mma16816(o[2 * dp],     ah, vlf[0], vlf[1]);
                mma16816(o[2 * dp],     al, vhf[0], vhf[1]);
                mma16816(o[2 * dp + 1], ah, vhf[2], vhf[3]);
                mma16816(o[2 * dp + 1], ah, vlf[2], vlf[3]);
                mma16816(o[2 * dp + 1], al, vhf[2], vhf[3]);
            }
        }

        // ---- rotate buffers ----
        CP_WAIT(0);
        __syncthreads();
        if (t + 2 < KTILES) {
            size_t off = (size_t)(t + 2) * 16384;
            copy_tile(sb + SM_BUF + (t & 1) * SM_BUFSZ,
                      kh_g + off, kl_g + off, vh_g + off, vl_g + off, tid);
            CP_COMMIT();
        }
    }

    // ---- reduce l over the 4 lanes sharing each row ----
    l0 += __shfl_xor_sync(0xffffffffu, l0, 1);
    l0 += __shfl_xor_sync(0xffffffffu, l0, 2);
    l1 += __shfl_xor_sync(0xffffffffu, l1, 1);
    l1 += __shfl_xor_sync(0xffffffffu, l1, 2);
    float inv0 = 1.0f / l0, inv1 = 1.0f / l1;

    float* d0 = &g_O[((size_t)(b * NTOK + r0)) * CDIM + h * 64];
    float* d1 = &g_O[((size_t)(b * NTOK + r0 + 8)) * CDIM + h * 64];
    #pragma unroll
    for (int dn = 0; dn < 8; dn++) {
        int d = 8 * dn + 2 * tc;
        float2 v0; v0.x = o[dn][0] * inv0; v0.y = o[dn][1] * inv0;
        float2 v1; v1.x = o[dn][2] * inv1; v1.y = o[dn][3] * inv1;
        *(float2*)&d0[d] = v0;
        *(float2*)&d1[d] = v1;
    }
}

// ============================================================================
// Kernel 3: output projection (SIMT f32x2, verified).
// ============================================================================
__global__ void __launch_bounds__(256) out_proj_kernel(
    const float* __restrict__ wo, const float* __restrict__ bo,
    float* __restrict__ y)
{
    const int n0  = blockIdx.x * 64;
    const int co0 = blockIdx.y * 64;
    const int b   = blockIdx.z;

    __shared__ float Os[64][68];
    __shared__ float Wos[64][65];

    const int tid = threadIdx.x;
    const int tx = tid & 15, ty = tid >> 4;
    const int lr = tid >> 4;
    const int lc = (tid & 15) * 4;

    unsigned long long acc2[4][2];
    #pragma unroll
    for (int i = 0; i < 4; i++) { acc2[i][0] = 0ull; acc2[i][1] = 0ull; }

    for (int c0 = 0; c0 < CDIM; c0 += 64) {
        #pragma unroll
        for (int rr = 0; rr < 4; rr++) {
            int n = lr + rr * 16;
            float4 v = *(const float4*)&g_O[((size_t)(b * NTOK + n0 + n)) * CDIM + c0 + lc];
            Os[lc + 0][n] = v.x; Os[lc + 1][n] = v.y;
            Os[lc + 2][n] = v.z; Os[lc + 3][n] = v.w;
        }
        #pragma unroll
        for (int rr = 0; rr < 4; rr++) {
            int co = lr + rr * 16;
            float4 v = *(const float4*)&wo[(size_t)(co0 + co) * CDIM + c0 + lc];
            Wos[co][lc + 0] = v.x; Wos[co][lc + 1] = v.y;
            Wos[co][lc + 2] = v.z; Wos[co][lc + 3] = v.w;
        }
        __syncthreads();

        #pragma unroll 8
        for (int c = 0; c < 64; c++) {
            ulonglong2 bu = *(const ulonglong2*)&Os[c][tx * 4];
            #pragma unroll
            for (int i = 0; i < 4; i++) {
                float a = Wos[ty * 4 + i][c];
                unsigned long long ad = pack2(a, a);
                ffma2(acc2[i][0], ad, bu.x);
                ffma2(acc2[i][1], ad, bu.y);
            }
        }
        __syncthreads();
    }

    #pragma unroll
    for (int i = 0; i < 4; i++) {
        int co = co0 + ty * 4 + i;
        float bbias = bo[co];
        float a0, a1, a2f, a3;
        unpack2(acc2[i][0], a0, a1);
        unpack2(acc2[i][1], a2f, a3);
        float4 v;
        v.x = a0 + bbias; v.y = a1 + bbias;
        v.z = a2f + bbias; v.w = a3 + bbias;
        *(float4*)&y[((size_t)(b * CDIM + co)) * NTOK + n0 + tx * 4] = v;
    }
}

// ============================================================================
// Launch
// ============================================================================
extern "C" void kernel_launch(void* const* d_in, const int* in_sizes, int n_in,
                              void* d_out, int out_size)
{
    const float* x    = (const float*)d_in[0];
    const int*   mask = (const int*)d_in[1];
    const float* wq   = (const float*)d_in[2];
    const float* bq   = (const float*)d_in[3];
    const float* wk   = (const float*)d_in[4];
    const float* bk   = (const float*)d_in[5];
    const float* wv   = (const float*)d_in[6];
    const float* bv   = (const float*)d_in[7];
    const float* wo   = (const float*)d_in[8];
    const float* bo   = (const float*)d_in[9];
    float* y = (float*)d_out;

    cudaFuncSetAttribute(attn_kernel,
                         cudaFuncAttributeMaxDynamicSharedMemorySize, ATTN_SMEM);

    qkv_proj_kernel<<<dim3(NTOK / 64, 12, BATCH), 256>>>(x, wq, bq, wk, bk, wv, bv);
    attn_kernel<<<dim3(NTOK / 128, BHDIM), 256, ATTN_SMEM>>>(mask);
    out_proj_kernel<<<dim3(NTOK / 64, CDIM / 64, BATCH), 256>>>(wo, bo, y);
}